// round 4
// baseline (speedup 1.0000x reference)
#include <cuda_runtime.h>
#include <math.h>

// Problem constants (fixed by the dataset)
#define N0   300000
#define N1   60000
#define N2   6000
#define E1C  1200000
#define E2C  300000
#define RR   4
#define DIN  128
#define DH   128
#define DOUT 64
#define NKEYS (N2*RR)          // 24000 (d,r) segments
#define KTOT  (RR*DH + DH)     // 640 concat K for layer-2 GEMM
#define BN_EPS 1e-5f

// ---------------- scratch (static device globals; no runtime allocation) ----
static __device__ __align__(16) float g_h[(size_t)N1 * DH];   // layer-1 output
static __device__ __align__(16) float g_A[(size_t)N2 * KTOT]; // layer-2 aggregates
static __device__ int   g_q[E1C];          // layer-1 edges whose dst is "needy"
static __device__ int   g_qcount;
static __device__ int   g_needy[N1];       // rows with history_map < 0
static __device__ int   g_ncount;
static __device__ float g_bnsum[DH];
static __device__ float g_bnsq[DH];
static __device__ float g_scale[DH];
static __device__ float g_shift[DH];
static __device__ __align__(16) int g_counts[NKEYS + 8];
static __device__ int   g_offsets[NKEYS + 1];
static __device__ int   g_cursor[NKEYS];
static __device__ __align__(16) int g_key[E2C];   // (dst*RR+et) per edge
static __device__ int   g_esrc[E2C];       // edge srcs sorted by (dst,rel)

// ---------------- K0: zero per-replay state -------------------------------
__global__ void k0_zero() {
    int i = blockIdx.x * blockDim.x + threadIdx.x;
    int stride = gridDim.x * blockDim.x;
    for (int idx = i; idx <= NKEYS; idx += stride) g_counts[idx] = 0;
    if (i < DH) { g_bnsum[i] = 0.f; g_bnsq[i] = 0.f; }
    if (i == 0) { g_qcount = 0; g_ncount = 0; }
}

// ---------------- K1: h = history gather + BN stats + needy list ----------
// Needy rows (map < 0) are zero-filled so later contributions can be adds.
__global__ void __launch_bounds__(256) k1_gather(const int* __restrict__ hmap,
                                                 const float4* __restrict__ hist4) {
    float s0=0.f,s1=0.f,s2=0.f,s3=0.f, q0=0.f,q1=0.f,q2=0.f,q3=0.f;
    const int total = N1 * 32;                 // float4 elements
    int stride = gridDim.x * blockDim.x;
    for (int i = blockIdx.x * blockDim.x + threadIdx.x; i < total; i += stride) {
        int d = i >> 5;
        int qq = i & 31;
        int m = __ldg(hmap + d);
        if (m >= 0) {
            float4 v = hist4[m * 32 + qq];
            reinterpret_cast<float4*>(g_h)[i] = v;
            s0 += v.x; q0 = fmaf(v.x, v.x, q0);
            s1 += v.y; q1 = fmaf(v.y, v.y, q1);
            s2 += v.z; q2 = fmaf(v.z, v.z, q2);
            s3 += v.w; q3 = fmaf(v.w, v.w, q3);
        } else {
            reinterpret_cast<float4*>(g_h)[i] = make_float4(0.f, 0.f, 0.f, 0.f);
            if (qq == 0) {
                int p = atomicAdd(&g_ncount, 1);
                g_needy[p] = d;
            }
        }
    }
    __shared__ float red[256][4];
    int t = threadIdx.x;
    red[t][0]=s0; red[t][1]=s1; red[t][2]=s2; red[t][3]=s3;
    __syncthreads();
    if (t < 32) {
        float a0=0.f,a1=0.f,a2=0.f,a3=0.f;
        #pragma unroll
        for (int w = 0; w < 8; w++) {
            a0 += red[t+32*w][0]; a1 += red[t+32*w][1];
            a2 += red[t+32*w][2]; a3 += red[t+32*w][3];
        }
        atomicAdd(&g_bnsum[t*4+0], a0); atomicAdd(&g_bnsum[t*4+1], a1);
        atomicAdd(&g_bnsum[t*4+2], a2); atomicAdd(&g_bnsum[t*4+3], a3);
    }
    __syncthreads();
    red[t][0]=q0; red[t][1]=q1; red[t][2]=q2; red[t][3]=q3;
    __syncthreads();
    if (t < 32) {
        float a0=0.f,a1=0.f,a2=0.f,a3=0.f;
        #pragma unroll
        for (int w = 0; w < 8; w++) {
            a0 += red[t+32*w][0]; a1 += red[t+32*w][1];
            a2 += red[t+32*w][2]; a3 += red[t+32*w][3];
        }
        atomicAdd(&g_bnsq[t*4+0], a0); atomicAdd(&g_bnsq[t*4+1], a1);
        atomicAdd(&g_bnsq[t*4+2], a2); atomicAdd(&g_bnsq[t*4+3], a3);
    }
}

// ---------------- K2a: needy-edge scan + layer-2 histogram + key cache ----
__global__ void __launch_bounds__(256) k2a_scan(
        const int* __restrict__ dst1, const int* __restrict__ hmap, int e1n,
        const int* __restrict__ dst2, const int* __restrict__ et2, int e2n) {
    int idx = blockIdx.x * blockDim.x + threadIdx.x;
    int stride = gridDim.x * blockDim.x;
    const int4* d14 = (const int4*)dst1;
    int n4 = e1n >> 2;
    for (int i = idx; i < n4; i += stride) {
        int4 dd = __ldg(d14 + i);
        int m0 = __ldg(hmap + dd.x), m1 = __ldg(hmap + dd.y);
        int m2 = __ldg(hmap + dd.z), m3 = __ldg(hmap + dd.w);
        if (m0 < 0) g_q[atomicAdd(&g_qcount, 1)] = 4*i + 0;
        if (m1 < 0) g_q[atomicAdd(&g_qcount, 1)] = 4*i + 1;
        if (m2 < 0) g_q[atomicAdd(&g_qcount, 1)] = 4*i + 2;
        if (m3 < 0) g_q[atomicAdd(&g_qcount, 1)] = 4*i + 3;
    }
    for (int e = (n4 << 2) + idx; e < e1n; e += stride)
        if (__ldg(hmap + __ldg(dst1 + e)) < 0)
            g_q[atomicAdd(&g_qcount, 1)] = e;
    // layer-2 histogram + key materialization
    const int4* d24 = (const int4*)dst2;
    const int4* t24 = (const int4*)et2;
    int4* k4 = (int4*)g_key;
    int h4 = e2n >> 2;
    for (int i = idx; i < h4; i += stride) {
        int4 dd = __ldg(d24 + i);
        int4 tt = __ldg(t24 + i);
        int4 kk = make_int4(dd.x * RR + tt.x, dd.y * RR + tt.y,
                            dd.z * RR + tt.z, dd.w * RR + tt.w);
        k4[i] = kk;
        atomicAdd(&g_counts[kk.x], 1);
        atomicAdd(&g_counts[kk.y], 1);
        atomicAdd(&g_counts[kk.z], 1);
        atomicAdd(&g_counts[kk.w], 1);
    }
    for (int e = (h4 << 2) + idx; e < e2n; e += stride) {
        int key = __ldg(dst2 + e) * RR + __ldg(et2 + e);
        g_key[e] = key;
        atomicAdd(&g_counts[key], 1);
    }
}

// ---------------- KNEEDY: self-transform + edge messages for needy rows ---
// Work items: [0, ncount) self rows (x[d] @ Wself1 + b1),
//             [ncount, ncount+qcount) edges (x[src] @ W1[r]).
// All contributions atomicAdd into zero-initialized g_h rows (commutative).
// 256 threads: col t = tid&127, K-half = tid>>7 (chain depth 64 -> 16 via
// 4 independent accumulators), then 2-way smem reduction.
__global__ void __launch_bounds__(256) kneedy(const float* __restrict__ x,
                                              const int* __restrict__ src1,
                                              const int* __restrict__ dst1,
                                              const int* __restrict__ et1,
                                              const float* __restrict__ W1,
                                              const float* __restrict__ Wself1,
                                              const float* __restrict__ b1) {
    __shared__ float xs[DIN];
    __shared__ float part[DIN];
    int tid = threadIdx.x;
    int t = tid & 127;
    int half = tid >> 7;
    int ncount = g_ncount;
    int total = ncount + g_qcount;
    for (int item = blockIdx.x; item < total; item += gridDim.x) {
        int d, s;
        const float* W;
        bool self = (item < ncount);
        if (self) {
            d = g_needy[item];
            s = d;
            W = Wself1;
        } else {
            int e = g_q[item - ncount];
            s = src1[e]; d = dst1[e];
            W = W1 + (size_t)et1[e] * DIN * DH;
        }
        if (tid < DIN) xs[tid] = x[(size_t)s * DIN + tid];
        __syncthreads();
        const float* w = W + (size_t)half * 64 * DH + t;
        float a0 = 0.f, a1 = 0.f, a2 = 0.f, a3 = 0.f;
        int base = half * 64;
        #pragma unroll
        for (int i = 0; i < 64; i += 4) {
            a0 = fmaf(xs[base + i + 0], w[(i + 0) * DH], a0);
            a1 = fmaf(xs[base + i + 1], w[(i + 1) * DH], a1);
            a2 = fmaf(xs[base + i + 2], w[(i + 2) * DH], a2);
            a3 = fmaf(xs[base + i + 3], w[(i + 3) * DH], a3);
        }
        float acc = (a0 + a1) + (a2 + a3);
        if (half) part[t] = acc;
        __syncthreads();
        if (!half) {
            float v = acc + part[t];
            if (self) v += b1[t];
            atomicAdd(&g_h[(size_t)d * DH + t], v);
        }
        __syncthreads();
    }
}

// ---------------- C3: needy BN patch + BN params + exclusive scan ---------
__global__ void c3_scan_bn(const float* __restrict__ gamma,
                           const float* __restrict__ beta) {
    int t = threadIdx.x;                          // 1024 threads
    if (t < DH) {
        float s = 0.f, ss = 0.f;
        int n = g_ncount;
        for (int j = 0; j < n; j++) {
            float v = g_h[(size_t)g_needy[j] * DH + t];
            s += v;
            ss = fmaf(v, v, ss);
        }
        float sum = g_bnsum[t] + s;
        float sq  = g_bnsq[t] + ss;
        float mean = sum * (1.0f / N1);
        float var  = sq * (1.0f / N1) - mean * mean;
        float sc   = gamma[t] * rsqrtf(var + BN_EPS);
        g_scale[t] = sc;
        g_shift[t] = beta[t] - mean * sc;
    }
    __shared__ int part[1024];
    const int CH = 24;                            // NKEYS / 1024 = 23.4 -> 24
    int beg = t * CH;                             // divisible by 4
    int cnt[CH];
    if (beg + CH <= NKEYS) {
        #pragma unroll
        for (int v = 0; v < 6; v++) {
            int4 c = *(const int4*)&g_counts[beg + 4 * v];
            cnt[4*v+0] = c.x; cnt[4*v+1] = c.y; cnt[4*v+2] = c.z; cnt[4*v+3] = c.w;
        }
    } else {
        #pragma unroll
        for (int v = 0; v < CH; v++)
            cnt[v] = (beg + v < NKEYS) ? g_counts[beg + v] : 0;
    }
    int s = 0;
    #pragma unroll
    for (int v = 0; v < CH; v++) s += cnt[v];
    part[t] = s;
    __syncthreads();
    for (int off = 1; off < 1024; off <<= 1) {
        int v = (t >= off) ? part[t - off] : 0;
        __syncthreads();
        part[t] += v;
        __syncthreads();
    }
    int run = part[t] - s;                        // exclusive prefix
    #pragma unroll
    for (int v = 0; v < CH; v++) {
        int i = beg + v;
        if (i < NKEYS) {
            g_offsets[i] = run;
            g_cursor[i]  = run;
            run += cnt[v];
        }
    }
    if (t == 1023) g_offsets[NKEYS] = run;
}

// ---------------- C4: scatter edge srcs into segment order ----------------
__global__ void __launch_bounds__(256) c4_scatter(const int* __restrict__ src2,
                                                  int e2n) {
    int idx = blockIdx.x * blockDim.x + threadIdx.x;
    int stride = gridDim.x * blockDim.x;
    const int4* s4 = (const int4*)src2;
    const int4* k4 = (const int4*)g_key;
    int n4 = e2n >> 2;
    for (int i = idx; i < n4; i += stride) {
        int4 ss = __ldg(s4 + i);
        int4 kk = k4[i];
        g_esrc[atomicAdd(&g_cursor[kk.x], 1)] = ss.x;
        g_esrc[atomicAdd(&g_cursor[kk.y], 1)] = ss.y;
        g_esrc[atomicAdd(&g_cursor[kk.z], 1)] = ss.z;
        g_esrc[atomicAdd(&g_cursor[kk.w], 1)] = ss.w;
    }
    for (int e = (n4 << 2) + idx; e < e2n; e += stride)
        g_esrc[atomicAdd(&g_cursor[g_key[e]], 1)] = __ldg(src2 + e);
}

// ---------------- K5a: per-(dst,rel) aggregation, one warp per segment ----
// Lane l owns cols [4l, 4l+4) as float4; 8 segments per 256-thread block.
__global__ void __launch_bounds__(256) k5a_agg() {
    int w = threadIdx.x >> 5;
    int l = threadIdx.x & 31;
    int seg = blockIdx.x * 8 + w;
    if (seg >= NKEYS) return;
    int d = seg >> 2, r = seg & 3;
    float4 sc = *(const float4*)&g_scale[4 * l];
    float4 sh = *(const float4*)&g_shift[4 * l];
    int beg = g_offsets[seg], end = g_offsets[seg + 1];
    float4 acc = make_float4(0.f, 0.f, 0.f, 0.f);
    int j = beg;
    for (; j + 4 <= end; j += 4) {
        int s0 = g_esrc[j + 0], s1 = g_esrc[j + 1];
        int s2 = g_esrc[j + 2], s3 = g_esrc[j + 3];
        float4 v0 = *(const float4*)&g_h[(size_t)s0 * DH + 4 * l];
        float4 v1 = *(const float4*)&g_h[(size_t)s1 * DH + 4 * l];
        float4 v2 = *(const float4*)&g_h[(size_t)s2 * DH + 4 * l];
        float4 v3 = *(const float4*)&g_h[(size_t)s3 * DH + 4 * l];
        acc.x += fmaxf(fmaf(sc.x, v0.x, sh.x), 0.f) + fmaxf(fmaf(sc.x, v1.x, sh.x), 0.f)
               + fmaxf(fmaf(sc.x, v2.x, sh.x), 0.f) + fmaxf(fmaf(sc.x, v3.x, sh.x), 0.f);
        acc.y += fmaxf(fmaf(sc.y, v0.y, sh.y), 0.f) + fmaxf(fmaf(sc.y, v1.y, sh.y), 0.f)
               + fmaxf(fmaf(sc.y, v2.y, sh.y), 0.f) + fmaxf(fmaf(sc.y, v3.y, sh.y), 0.f);
        acc.z += fmaxf(fmaf(sc.z, v0.z, sh.z), 0.f) + fmaxf(fmaf(sc.z, v1.z, sh.z), 0.f)
               + fmaxf(fmaf(sc.z, v2.z, sh.z), 0.f) + fmaxf(fmaf(sc.z, v3.z, sh.z), 0.f);
        acc.w += fmaxf(fmaf(sc.w, v0.w, sh.w), 0.f) + fmaxf(fmaf(sc.w, v1.w, sh.w), 0.f)
               + fmaxf(fmaf(sc.w, v2.w, sh.w), 0.f) + fmaxf(fmaf(sc.w, v3.w, sh.w), 0.f);
    }
    for (; j < end; j++) {
        float4 v = *(const float4*)&g_h[(size_t)g_esrc[j] * DH + 4 * l];
        acc.x += fmaxf(fmaf(sc.x, v.x, sh.x), 0.f);
        acc.y += fmaxf(fmaf(sc.y, v.y, sh.y), 0.f);
        acc.z += fmaxf(fmaf(sc.z, v.z, sh.z), 0.f);
        acc.w += fmaxf(fmaf(sc.w, v.w, sh.w), 0.f);
    }
    float* Ad = g_A + (size_t)d * KTOT;
    *(float4*)&Ad[r * DH + 4 * l] = acc;
    if (r == 0) {                                // self-loop (d < N2 <= N1)
        float4 v = *(const float4*)&g_h[(size_t)d * DH + 4 * l];
        float4 sv = make_float4(fmaxf(fmaf(sc.x, v.x, sh.x), 0.f),
                                fmaxf(fmaf(sc.y, v.y, sh.y), 0.f),
                                fmaxf(fmaf(sc.z, v.z, sh.z), 0.f),
                                fmaxf(fmaf(sc.w, v.w, sh.w), 0.f));
        *(float4*)&Ad[RR * DH + 4 * l] = sv;
    }
}

// ---------------- K5b: tiled GEMM [6000,640]x[640,64] + bias + log-softmax
#define TMB 32
#define KB  16
#define NCH (KTOT / KB)      // 40

__global__ void __launch_bounds__(128) k5b_gemm(const float* __restrict__ W2,
                                                const float* __restrict__ Wself2,
                                                const float* __restrict__ b2,
                                                float* __restrict__ out) {
    __shared__ float As[KB][TMB + 4];            // stride 36 floats
    __shared__ float Ws[KB][DOUT];
    int tid = threadIdx.x;
    int tc = tid & 15;                           // col group (4 cols)
    int tr = tid >> 4;                           // row group (4 rows), 0..7
    int row0 = blockIdx.x * TMB;

    int m_l = tid >> 2;                          // 0..31
    int k_l = (tid & 3) * 4;                     // 0,4,8,12
    int arow = min(row0 + m_l, N2 - 1);
    const float* Ab = g_A + (size_t)arow * KTOT + k_l;

    int k_w = tid >> 3;                          // 0..15
    int c_w = (tid & 7) * 8;                     // 0..56

    float4 pa, pw0, pw1;
    pa = *(const float4*)Ab;
    {
        const float* wp = W2 + (size_t)k_w * DOUT + c_w;   // chunk 0: k < 512
        pw0 = *(const float4*)wp;
        pw1 = *(const float4*)(wp + 4);
    }

    float acc[4][4];
    #pragma unroll
    for (int m = 0; m < 4; m++)
        #pragma unroll
        for (int c = 0; c < 4; c++) acc[m][c] = 0.f;

    for (int kc = 0; kc < NCH; kc++) {
        __syncthreads();
        As[k_l + 0][m_l] = pa.x;
        As[k_l + 1][m_l] = pa.y;
        As[k_l + 2][m_l] = pa.z;
        As[k_l + 3][m_l] = pa.w;
        *(float4*)&Ws[k_w][c_w]     = pw0;
        *(float4*)&Ws[k_w][c_w + 4] = pw1;
        __syncthreads();
        if (kc + 1 < NCH) {
            pa = *(const float4*)(Ab + (kc + 1) * KB);
            int kk = (kc + 1) * KB + k_w;
            const float* wp = (kk < RR * DH)
                ? W2 + (size_t)kk * DOUT + c_w
                : Wself2 + (size_t)(kk - RR * DH) * DOUT + c_w;
            pw0 = *(const float4*)wp;
            pw1 = *(const float4*)(wp + 4);
        }
        #pragma unroll
        for (int k = 0; k < KB; k++) {
            float4 a = *(float4*)&As[k][tr * 4];
            float4 w = *(float4*)&Ws[k][tc * 4];
            acc[0][0] = fmaf(a.x, w.x, acc[0][0]);
            acc[0][1] = fmaf(a.x, w.y, acc[0][1]);
            acc[0][2] = fmaf(a.x, w.z, acc[0][2]);
            acc[0][3] = fmaf(a.x, w.w, acc[0][3]);
            acc[1][0] = fmaf(a.y, w.x, acc[1][0]);
            acc[1][1] = fmaf(a.y, w.y, acc[1][1]);
            acc[1][2] = fmaf(a.y, w.z, acc[1][2]);
            acc[1][3] = fmaf(a.y, w.w, acc[1][3]);
            acc[2][0] = fmaf(a.z, w.x, acc[2][0]);
            acc[2][1] = fmaf(a.z, w.y, acc[2][1]);
            acc[2][2] = fmaf(a.z, w.z, acc[2][2]);
            acc[2][3] = fmaf(a.z, w.w, acc[2][3]);
            acc[3][0] = fmaf(a.w, w.x, acc[3][0]);
            acc[3][1] = fmaf(a.w, w.y, acc[3][1]);
            acc[3][2] = fmaf(a.w, w.z, acc[3][2]);
            acc[3][3] = fmaf(a.w, w.w, acc[3][3]);
        }
    }

    // epilogue: bias + log-softmax per row (16 lanes share one row)
    float4 bb = *(const float4*)(b2 + tc * 4);
    #pragma unroll
    for (int m = 0; m < 4; m++) {
        int row = row0 + tr * 4 + m;
        float v0 = acc[m][0] + bb.x;
        float v1 = acc[m][1] + bb.y;
        float v2 = acc[m][2] + bb.z;
        float v3 = acc[m][3] + bb.w;
        float mx = fmaxf(fmaxf(v0, v1), fmaxf(v2, v3));
        #pragma unroll
        for (int off = 1; off < 16; off <<= 1)
            mx = fmaxf(mx, __shfl_xor_sync(0xffffffffu, mx, off));
        float es = expf(v0 - mx) + expf(v1 - mx) + expf(v2 - mx) + expf(v3 - mx);
        #pragma unroll
        for (int off = 1; off < 16; off <<= 1)
            es += __shfl_xor_sync(0xffffffffu, es, off);
        float l = mx + logf(es);
        if (row < N2) {
            float4 o = make_float4(v0 - l, v1 - l, v2 - l, v3 - l);
            *(float4*)(out + (size_t)row * DOUT + tc * 4) = o;
        }
    }
}

// ---------------- launch ---------------------------------------------------
extern "C" void kernel_launch(void* const* d_in, const int* in_sizes, int n_in,
                              void* d_out, int out_size) {
    const float* x      = (const float*)d_in[0];
    const int*   src1   = (const int*)d_in[1];
    const int*   dst1   = (const int*)d_in[2];
    const int*   et1    = (const int*)d_in[3];
    const int*   src2   = (const int*)d_in[4];
    const int*   dst2   = (const int*)d_in[5];
    const int*   et2    = (const int*)d_in[6];
    const int*   hmap   = (const int*)d_in[7];
    const float* hist   = (const float*)d_in[8];
    const float* W1     = (const float*)d_in[9];
    const float* Wself1 = (const float*)d_in[10];
    const float* b1     = (const float*)d_in[11];
    const float* gamma  = (const float*)d_in[12];
    const float* beta   = (const float*)d_in[13];
    const float* W2     = (const float*)d_in[14];
    const float* Wself2 = (const float*)d_in[15];
    const float* b2     = (const float*)d_in[16];
    float* out = (float*)d_out;

    int e1n = in_sizes[1];
    int e2n = in_sizes[4];

    k0_zero<<<96, 256>>>();
    k1_gather<<<2048, 256>>>(hmap, (const float4*)hist);
    k2a_scan<<<2048, 256>>>(dst1, hmap, e1n, dst2, et2, e2n);
    kneedy<<<64, 256>>>(x, src1, dst1, et1, W1, Wself1, b1);
    c3_scan_bn<<<1, 1024>>>(gamma, beta);
    c4_scatter<<<1024, 256>>>(src2, e2n);
    k5a_agg<<<(NKEYS + 7) / 8, 256>>>();
    k5b_gemm<<<(N2 + TMB - 1) / TMB, 128>>>(W2, Wself2, b2, out);
}

// round 5
// speedup vs baseline: 1.2554x; 1.2554x over previous
#include <cuda_runtime.h>
#include <math.h>

// Problem constants (fixed by the dataset)
#define N0   300000
#define N1   60000
#define N2   6000
#define E1C  1200000
#define E2C  300000
#define RR   4
#define DIN  128
#define DH   128
#define DOUT 64
#define NKEYS (N2*RR)          // 24000 (d,r) segments
#define KTOT  (RR*DH + DH)     // 640 concat K for layer-2 GEMM
#define BN_EPS 1e-5f

// ---------------- scratch (static device globals; no runtime allocation) ----
static __device__ __align__(16) float g_h[(size_t)N1 * DH];   // layer-1 output
static __device__ __align__(16) float g_A[(size_t)N2 * KTOT]; // layer-2 aggregates
static __device__ int   g_q[E1C];          // layer-1 edges whose dst is "needy"
static __device__ int   g_qcount;
static __device__ int   g_needy[N1];       // rows with history_map < 0
static __device__ int   g_ncount;
static __device__ float g_bnsum[DH];
static __device__ float g_bnsq[DH];
static __device__ float g_scale[DH];
static __device__ float g_shift[DH];
static __device__ int   g_counts[NKEYS + 1];
static __device__ int   g_offsets[NKEYS + 1];
static __device__ int   g_cursor[NKEYS];
static __device__ int   g_esrc[E2C];       // edge srcs sorted by (dst,rel)

// ---------------- K0: zero per-replay state -------------------------------
__global__ void k0_zero() {
    int i = blockIdx.x * blockDim.x + threadIdx.x;
    int stride = gridDim.x * blockDim.x;
    for (int idx = i; idx <= NKEYS; idx += stride) g_counts[idx] = 0;
    if (i < DH) { g_bnsum[i] = 0.f; g_bnsq[i] = 0.f; }
    if (i == 0) { g_qcount = 0; g_ncount = 0; }
}

// ---------------- K1: h = history gather + BN partial stats + needy list --
// Needy rows (map < 0) are zero-filled so kneedy can accumulate with adds.
__global__ void __launch_bounds__(256) k1_gather(const int* __restrict__ hmap,
                                                 const float4* __restrict__ hist4) {
    float s0=0.f,s1=0.f,s2=0.f,s3=0.f, q0=0.f,q1=0.f,q2=0.f,q3=0.f;
    const int total = N1 * 32;                 // float4 elements
    int stride = gridDim.x * blockDim.x;       // multiple of 32
    for (int i = blockIdx.x * blockDim.x + threadIdx.x; i < total; i += stride) {
        int d = i >> 5;
        int qq = i & 31;
        int m = __ldg(hmap + d);
        if (m >= 0) {
            float4 v = hist4[m * 32 + qq];
            reinterpret_cast<float4*>(g_h)[i] = v;
            s0 += v.x; q0 = fmaf(v.x, v.x, q0);
            s1 += v.y; q1 = fmaf(v.y, v.y, q1);
            s2 += v.z; q2 = fmaf(v.z, v.z, q2);
            s3 += v.w; q3 = fmaf(v.w, v.w, q3);
        } else {
            reinterpret_cast<float4*>(g_h)[i] = make_float4(0.f, 0.f, 0.f, 0.f);
            if (qq == 0) {
                int p = atomicAdd(&g_ncount, 1);
                g_needy[p] = d;
            }
        }
    }
    __shared__ float red[256][4];
    int t = threadIdx.x;
    red[t][0]=s0; red[t][1]=s1; red[t][2]=s2; red[t][3]=s3;
    __syncthreads();
    if (t < 32) {
        float a0=0.f,a1=0.f,a2=0.f,a3=0.f;
        #pragma unroll
        for (int w = 0; w < 8; w++) {
            a0 += red[t+32*w][0]; a1 += red[t+32*w][1];
            a2 += red[t+32*w][2]; a3 += red[t+32*w][3];
        }
        atomicAdd(&g_bnsum[t*4+0], a0); atomicAdd(&g_bnsum[t*4+1], a1);
        atomicAdd(&g_bnsum[t*4+2], a2); atomicAdd(&g_bnsum[t*4+3], a3);
    }
    __syncthreads();
    red[t][0]=q0; red[t][1]=q1; red[t][2]=q2; red[t][3]=q3;
    __syncthreads();
    if (t < 32) {
        float a0=0.f,a1=0.f,a2=0.f,a3=0.f;
        #pragma unroll
        for (int w = 0; w < 8; w++) {
            a0 += red[t+32*w][0]; a1 += red[t+32*w][1];
            a2 += red[t+32*w][2]; a3 += red[t+32*w][3];
        }
        atomicAdd(&g_bnsq[t*4+0], a0); atomicAdd(&g_bnsq[t*4+1], a1);
        atomicAdd(&g_bnsq[t*4+2], a2); atomicAdd(&g_bnsq[t*4+3], a3);
    }
}

// ---------------- K2a: scan layer-1 edges for needy dsts + layer-2 hist ---
__global__ void __launch_bounds__(256) k2a_scan(
        const int* __restrict__ dst1, const int* __restrict__ hmap, int e1n,
        const int* __restrict__ dst2, const int* __restrict__ et2, int e2n) {
    int idx = blockIdx.x * blockDim.x + threadIdx.x;
    int stride = gridDim.x * blockDim.x;
    const int4* d14 = (const int4*)dst1;
    int n4 = e1n >> 2;
    for (int i = idx; i < n4; i += stride) {
        int4 dd = __ldg(d14 + i);
        int m0 = __ldg(hmap + dd.x), m1 = __ldg(hmap + dd.y);
        int m2 = __ldg(hmap + dd.z), m3 = __ldg(hmap + dd.w);
        if (m0 < 0) g_q[atomicAdd(&g_qcount, 1)] = 4*i + 0;
        if (m1 < 0) g_q[atomicAdd(&g_qcount, 1)] = 4*i + 1;
        if (m2 < 0) g_q[atomicAdd(&g_qcount, 1)] = 4*i + 2;
        if (m3 < 0) g_q[atomicAdd(&g_qcount, 1)] = 4*i + 3;
    }
    for (int e = (n4 << 2) + idx; e < e1n; e += stride)
        if (__ldg(hmap + __ldg(dst1 + e)) < 0)
            g_q[atomicAdd(&g_qcount, 1)] = e;
    // layer-2 histogram
    const int4* d24 = (const int4*)dst2;
    const int4* t24 = (const int4*)et2;
    int h4 = e2n >> 2;
    for (int i = idx; i < h4; i += stride) {
        int4 dd = __ldg(d24 + i);
        int4 tt = __ldg(t24 + i);
        atomicAdd(&g_counts[dd.x * RR + tt.x], 1);
        atomicAdd(&g_counts[dd.y * RR + tt.y], 1);
        atomicAdd(&g_counts[dd.z * RR + tt.z], 1);
        atomicAdd(&g_counts[dd.w * RR + tt.w], 1);
    }
    for (int e = (h4 << 2) + idx; e < e2n; e += stride)
        atomicAdd(&g_counts[__ldg(dst2 + e) * RR + __ldg(et2 + e)], 1);
}

// ---------------- KNEEDY: self-transform + edge messages for needy rows ---
// Work items: [0, ncount) self rows (x[d] @ Wself1 + b1),
//             [ncount, ncount+qcount) edges (x[src] @ W1[r]).
// All contributions atomicAdd into zero-initialized g_h rows (commutative).
__global__ void __launch_bounds__(256) kneedy(const float* __restrict__ x,
                                              const int* __restrict__ src1,
                                              const int* __restrict__ dst1,
                                              const int* __restrict__ et1,
                                              const float* __restrict__ W1,
                                              const float* __restrict__ Wself1,
                                              const float* __restrict__ b1) {
    __shared__ float xs[DIN];
    __shared__ float part[DIN];
    int tid = threadIdx.x;
    int t = tid & 127;
    int half = tid >> 7;
    int ncount = g_ncount;
    int total = ncount + g_qcount;
    for (int item = blockIdx.x; item < total; item += gridDim.x) {
        int d, s;
        const float* W;
        bool self = (item < ncount);
        if (self) {
            d = g_needy[item];
            s = d;
            W = Wself1;
        } else {
            int e = g_q[item - ncount];
            s = src1[e]; d = dst1[e];
            W = W1 + (size_t)et1[e] * DIN * DH;
        }
        if (tid < DIN) xs[tid] = x[(size_t)s * DIN + tid];
        __syncthreads();
        const float* w = W + (size_t)half * 64 * DH + t;
        float a0 = 0.f, a1 = 0.f, a2 = 0.f, a3 = 0.f;
        int base = half * 64;
        #pragma unroll
        for (int i = 0; i < 64; i += 4) {
            a0 = fmaf(xs[base + i + 0], w[(i + 0) * DH], a0);
            a1 = fmaf(xs[base + i + 1], w[(i + 1) * DH], a1);
            a2 = fmaf(xs[base + i + 2], w[(i + 2) * DH], a2);
            a3 = fmaf(xs[base + i + 3], w[(i + 3) * DH], a3);
        }
        float acc = (a0 + a1) + (a2 + a3);
        if (half) part[t] = acc;
        __syncthreads();
        if (!half) {
            float v = acc + part[t];
            if (self) v += b1[t];
            atomicAdd(&g_h[(size_t)d * DH + t], v);
        }
        __syncthreads();
    }
}

// ---------------- C3: needy BN patch + BN params + exclusive scan ---------
__global__ void c3_scan_bn(const float* __restrict__ gamma,
                           const float* __restrict__ beta) {
    int t = threadIdx.x;                          // 1024 threads
    if (t < DH) {
        float s = 0.f, ss = 0.f;
        int n = g_ncount;
        for (int j = 0; j < n; j++) {
            float v = g_h[(size_t)g_needy[j] * DH + t];
            s += v;
            ss = fmaf(v, v, ss);
        }
        float sum = g_bnsum[t] + s;
        float sq  = g_bnsq[t] + ss;
        float mean = sum * (1.0f / N1);
        float var  = sq * (1.0f / N1) - mean * mean;
        float sc   = gamma[t] * rsqrtf(var + BN_EPS);
        g_scale[t] = sc;
        g_shift[t] = beta[t] - mean * sc;
    }
    __shared__ int part[1024];
    const int CH = (NKEYS + 1023) / 1024;        // 24
    int beg = t * CH;
    int end = min(beg + CH, NKEYS);
    int s = 0;
    for (int i = beg; i < end; i++) s += g_counts[i];
    part[t] = s;
    __syncthreads();
    for (int off = 1; off < 1024; off <<= 1) {
        int v = (t >= off) ? part[t - off] : 0;
        __syncthreads();
        part[t] += v;
        __syncthreads();
    }
    int run = part[t] - s;                        // exclusive prefix
    for (int i = beg; i < end; i++) {
        g_offsets[i] = run;
        g_cursor[i]  = run;
        run += g_counts[i];
    }
    if (t == 1023) g_offsets[NKEYS] = part[1023];
}

// ---------------- C4: scatter edge srcs into segment order ----------------
__global__ void __launch_bounds__(256) c4_scatter(
        const int* __restrict__ src2, const int* __restrict__ dst2,
        const int* __restrict__ et2, int e2n) {
    int idx = blockIdx.x * blockDim.x + threadIdx.x;
    int stride = gridDim.x * blockDim.x;
    const int4* s4 = (const int4*)src2;
    const int4* d4 = (const int4*)dst2;
    const int4* t4 = (const int4*)et2;
    int n4 = e2n >> 2;
    for (int i = idx; i < n4; i += stride) {
        int4 ss = __ldg(s4 + i);
        int4 dd = __ldg(d4 + i);
        int4 tt = __ldg(t4 + i);
        g_esrc[atomicAdd(&g_cursor[dd.x * RR + tt.x], 1)] = ss.x;
        g_esrc[atomicAdd(&g_cursor[dd.y * RR + tt.y], 1)] = ss.y;
        g_esrc[atomicAdd(&g_cursor[dd.z * RR + tt.z], 1)] = ss.z;
        g_esrc[atomicAdd(&g_cursor[dd.w * RR + tt.w], 1)] = ss.w;
    }
    for (int e = (n4 << 2) + idx; e < e2n; e += stride) {
        int key = __ldg(dst2 + e) * RR + __ldg(et2 + e);
        g_esrc[atomicAdd(&g_cursor[key], 1)] = __ldg(src2 + e);
    }
}

// ---------------- K5a: per-dst aggregation (BN+ReLU on the fly) -----------
__global__ void __launch_bounds__(128) k5a_agg() {
    int d = blockIdx.x;                          // one block per dst row
    int t = threadIdx.x;                         // 128 threads = feature col
    float sc = g_scale[t], sh = g_shift[t];
    float* Ad = g_A + (size_t)d * KTOT;
    #pragma unroll
    for (int r = 0; r < RR; r++) {
        int beg = g_offsets[d * RR + r];
        int end = g_offsets[d * RR + r + 1];
        float acc = 0.f;
        int j = beg;
        for (; j + 4 <= end; j += 4) {
            int s0 = g_esrc[j], s1 = g_esrc[j + 1];
            int s2 = g_esrc[j + 2], s3 = g_esrc[j + 3];
            float v0 = g_h[(size_t)s0 * DH + t];
            float v1 = g_h[(size_t)s1 * DH + t];
            float v2 = g_h[(size_t)s2 * DH + t];
            float v3 = g_h[(size_t)s3 * DH + t];
            acc += fmaxf(fmaf(sc, v0, sh), 0.f);
            acc += fmaxf(fmaf(sc, v1, sh), 0.f);
            acc += fmaxf(fmaf(sc, v2, sh), 0.f);
            acc += fmaxf(fmaf(sc, v3, sh), 0.f);
        }
        for (; j < end; j++) {
            float v = g_h[(size_t)g_esrc[j] * DH + t];
            acc += fmaxf(fmaf(sc, v, sh), 0.f);
        }
        Ad[r * DH + t] = acc;
    }
    // self-loop input (d < N2 <= N1)
    Ad[RR * DH + t] = fmaxf(fmaf(sc, g_h[(size_t)d * DH + t], sh), 0.f);
}

// ---------------- K5b: tiled GEMM [6000,640]x[640,64] + bias + log-softmax
#define TMB 32
#define KB  16
#define NCH (KTOT / KB)      // 40

__global__ void __launch_bounds__(128) k5b_gemm(const float* __restrict__ W2,
                                                const float* __restrict__ Wself2,
                                                const float* __restrict__ b2,
                                                float* __restrict__ out) {
    __shared__ float As[KB][TMB + 4];            // stride 36 floats
    __shared__ float Ws[KB][DOUT];
    int tid = threadIdx.x;
    int tc = tid & 15;                           // col group (4 cols)
    int tr = tid >> 4;                           // row group (4 rows), 0..7
    int row0 = blockIdx.x * TMB;

    int m_l = tid >> 2;                          // 0..31
    int k_l = (tid & 3) * 4;                     // 0,4,8,12
    int arow = min(row0 + m_l, N2 - 1);
    const float* Ab = g_A + (size_t)arow * KTOT + k_l;

    int k_w = tid >> 3;                          // 0..15
    int c_w = (tid & 7) * 8;                     // 0..56

    float4 pa, pw0, pw1;
    pa = *(const float4*)Ab;
    {
        const float* wp = W2 + (size_t)k_w * DOUT + c_w;   // chunk 0: k < 512
        pw0 = *(const float4*)wp;
        pw1 = *(const float4*)(wp + 4);
    }

    float acc[4][4];
    #pragma unroll
    for (int m = 0; m < 4; m++)
        #pragma unroll
        for (int c = 0; c < 4; c++) acc[m][c] = 0.f;

    for (int kc = 0; kc < NCH; kc++) {
        __syncthreads();
        As[k_l + 0][m_l] = pa.x;
        As[k_l + 1][m_l] = pa.y;
        As[k_l + 2][m_l] = pa.z;
        As[k_l + 3][m_l] = pa.w;
        *(float4*)&Ws[k_w][c_w]     = pw0;
        *(float4*)&Ws[k_w][c_w + 4] = pw1;
        __syncthreads();
        if (kc + 1 < NCH) {
            pa = *(const float4*)(Ab + (kc + 1) * KB);
            int kk = (kc + 1) * KB + k_w;
            const float* wp = (kk < RR * DH)
                ? W2 + (size_t)kk * DOUT + c_w
                : Wself2 + (size_t)(kk - RR * DH) * DOUT + c_w;
            pw0 = *(const float4*)wp;
            pw1 = *(const float4*)(wp + 4);
        }
        #pragma unroll
        for (int k = 0; k < KB; k++) {
            float4 a = *(float4*)&As[k][tr * 4];
            float4 w = *(float4*)&Ws[k][tc * 4];
            acc[0][0] = fmaf(a.x, w.x, acc[0][0]);
            acc[0][1] = fmaf(a.x, w.y, acc[0][1]);
            acc[0][2] = fmaf(a.x, w.z, acc[0][2]);
            acc[0][3] = fmaf(a.x, w.w, acc[0][3]);
            acc[1][0] = fmaf(a.y, w.x, acc[1][0]);
            acc[1][1] = fmaf(a.y, w.y, acc[1][1]);
            acc[1][2] = fmaf(a.y, w.z, acc[1][2]);
            acc[1][3] = fmaf(a.y, w.w, acc[1][3]);
            acc[2][0] = fmaf(a.z, w.x, acc[2][0]);
            acc[2][1] = fmaf(a.z, w.y, acc[2][1]);
            acc[2][2] = fmaf(a.z, w.z, acc[2][2]);
            acc[2][3] = fmaf(a.z, w.w, acc[2][3]);
            acc[3][0] = fmaf(a.w, w.x, acc[3][0]);
            acc[3][1] = fmaf(a.w, w.y, acc[3][1]);
            acc[3][2] = fmaf(a.w, w.z, acc[3][2]);
            acc[3][3] = fmaf(a.w, w.w, acc[3][3]);
        }
    }

    // epilogue: bias + log-softmax per row (16 lanes share one row)
    float4 bb = *(const float4*)(b2 + tc * 4);
    #pragma unroll
    for (int m = 0; m < 4; m++) {
        int row = row0 + tr * 4 + m;
        float v0 = acc[m][0] + bb.x;
        float v1 = acc[m][1] + bb.y;
        float v2 = acc[m][2] + bb.z;
        float v3 = acc[m][3] + bb.w;
        float mx = fmaxf(fmaxf(v0, v1), fmaxf(v2, v3));
        #pragma unroll
        for (int off = 1; off < 16; off <<= 1)
            mx = fmaxf(mx, __shfl_xor_sync(0xffffffffu, mx, off));
        float es = expf(v0 - mx) + expf(v1 - mx) + expf(v2 - mx) + expf(v3 - mx);
        #pragma unroll
        for (int off = 1; off < 16; off <<= 1)
            es += __shfl_xor_sync(0xffffffffu, es, off);
        float l = mx + logf(es);
        if (row < N2) {
            float4 o = make_float4(v0 - l, v1 - l, v2 - l, v3 - l);
            *(float4*)(out + (size_t)row * DOUT + tc * 4) = o;
        }
    }
}

// ---------------- launch ---------------------------------------------------
extern "C" void kernel_launch(void* const* d_in, const int* in_sizes, int n_in,
                              void* d_out, int out_size) {
    const float* x      = (const float*)d_in[0];
    const int*   src1   = (const int*)d_in[1];
    const int*   dst1   = (const int*)d_in[2];
    const int*   et1    = (const int*)d_in[3];
    const int*   src2   = (const int*)d_in[4];
    const int*   dst2   = (const int*)d_in[5];
    const int*   et2    = (const int*)d_in[6];
    const int*   hmap   = (const int*)d_in[7];
    const float* hist   = (const float*)d_in[8];
    const float* W1     = (const float*)d_in[9];
    const float* Wself1 = (const float*)d_in[10];
    const float* b1     = (const float*)d_in[11];
    const float* gamma  = (const float*)d_in[12];
    const float* beta   = (const float*)d_in[13];
    const float* W2     = (const float*)d_in[14];
    const float* Wself2 = (const float*)d_in[15];
    const float* b2     = (const float*)d_in[16];
    float* out = (float*)d_out;

    int e1n = in_sizes[1];
    int e2n = in_sizes[4];

    k0_zero<<<96, 256>>>();
    k1_gather<<<512, 256>>>(hmap, (const float4*)hist);
    k2a_scan<<<2048, 256>>>(dst1, hmap, e1n, dst2, et2, e2n);
    kneedy<<<64, 256>>>(x, src1, dst1, et1, W1, Wself1, b1);
    c3_scan_bn<<<1, 1024>>>(gamma, beta);
    c4_scatter<<<1024, 256>>>(src2, dst2, et2, e2n);
    k5a_agg<<<N2, 128>>>();
    k5b_gemm<<<(N2 + TMB - 1) / TMB, 128>>>(W2, Wself2, b2, out);
}

// round 7
// speedup vs baseline: 1.3847x; 1.1029x over previous
#include <cuda_runtime.h>
#include <math.h>

// Problem constants (fixed by the dataset)
#define N0   300000
#define N1   60000
#define N2   6000
#define E1C  1200000
#define E2C  300000
#define RR   4
#define DIN  128
#define DH   128
#define DOUT 64
#define NKEYS (N2*RR)          // 24000 (d,r) segments
#define KTOT  (RR*DH + DH)     // 640 concat K for layer-2 GEMM
#define BN_EPS 1e-5f

// ---------------- scratch (static device globals; no runtime allocation) ----
static __device__ __align__(16) float g_h[(size_t)N1 * DH];   // layer-1 output
static __device__ __align__(16) float g_A[(size_t)N2 * KTOT]; // layer-2 aggregates
static __device__ int   g_q[E1C];          // layer-1 edges whose dst is "needy"
static __device__ int   g_qcount;
static __device__ int   g_needy[N1];       // rows with history_map < 0
static __device__ int   g_ncount;
static __device__ float g_bnsum[DH];
static __device__ float g_bnsq[DH];
static __device__ float g_scale[DH];
static __device__ float g_shift[DH];
static __device__ int   g_counts[NKEYS + 1];
static __device__ int   g_offsets[NKEYS + 1];
static __device__ int   g_cursor[NKEYS];
static __device__ int   g_esrc[E2C];       // edge srcs sorted by (dst,rel)

// ---------------- K0: zero per-replay state -------------------------------
__global__ void k0_zero() {
    int i = blockIdx.x * blockDim.x + threadIdx.x;
    int stride = gridDim.x * blockDim.x;
    for (int idx = i; idx <= NKEYS; idx += stride) g_counts[idx] = 0;
    if (i < DH) { g_bnsum[i] = 0.f; g_bnsq[i] = 0.f; }
    if (i == 0) { g_qcount = 0; g_ncount = 0; }
}

// ---------------- K1: h = history gather + BN partial stats + needy list --
// Needy rows (map < 0) are zero-filled so kneedy can accumulate with adds.
__global__ void __launch_bounds__(256) k1_gather(const int* __restrict__ hmap,
                                                 const float4* __restrict__ hist4) {
    float s0=0.f,s1=0.f,s2=0.f,s3=0.f, q0=0.f,q1=0.f,q2=0.f,q3=0.f;
    const int total = N1 * 32;                 // float4 elements
    int stride = gridDim.x * blockDim.x;       // multiple of 32
    for (int i = blockIdx.x * blockDim.x + threadIdx.x; i < total; i += stride) {
        int d = i >> 5;
        int qq = i & 31;
        int m = __ldg(hmap + d);
        if (m >= 0) {
            float4 v = hist4[m * 32 + qq];
            reinterpret_cast<float4*>(g_h)[i] = v;
            s0 += v.x; q0 = fmaf(v.x, v.x, q0);
            s1 += v.y; q1 = fmaf(v.y, v.y, q1);
            s2 += v.z; q2 = fmaf(v.z, v.z, q2);
            s3 += v.w; q3 = fmaf(v.w, v.w, q3);
        } else {
            reinterpret_cast<float4*>(g_h)[i] = make_float4(0.f, 0.f, 0.f, 0.f);
            if (qq == 0) {
                int p = atomicAdd(&g_ncount, 1);
                g_needy[p] = d;
            }
        }
    }
    __shared__ float red[256][4];
    int t = threadIdx.x;
    red[t][0]=s0; red[t][1]=s1; red[t][2]=s2; red[t][3]=s3;
    __syncthreads();
    if (t < 32) {
        float a0=0.f,a1=0.f,a2=0.f,a3=0.f;
        #pragma unroll
        for (int w = 0; w < 8; w++) {
            a0 += red[t+32*w][0]; a1 += red[t+32*w][1];
            a2 += red[t+32*w][2]; a3 += red[t+32*w][3];
        }
        atomicAdd(&g_bnsum[t*4+0], a0); atomicAdd(&g_bnsum[t*4+1], a1);
        atomicAdd(&g_bnsum[t*4+2], a2); atomicAdd(&g_bnsum[t*4+3], a3);
    }
    __syncthreads();
    red[t][0]=q0; red[t][1]=q1; red[t][2]=q2; red[t][3]=q3;
    __syncthreads();
    if (t < 32) {
        float a0=0.f,a1=0.f,a2=0.f,a3=0.f;
        #pragma unroll
        for (int w = 0; w < 8; w++) {
            a0 += red[t+32*w][0]; a1 += red[t+32*w][1];
            a2 += red[t+32*w][2]; a3 += red[t+32*w][3];
        }
        atomicAdd(&g_bnsq[t*4+0], a0); atomicAdd(&g_bnsq[t*4+1], a1);
        atomicAdd(&g_bnsq[t*4+2], a2); atomicAdd(&g_bnsq[t*4+3], a3);
    }
}

// ---------------- K2a: scan layer-1 edges for needy dsts + layer-2 hist ---
__global__ void __launch_bounds__(256) k2a_scan(
        const int* __restrict__ dst1, const int* __restrict__ hmap, int e1n,
        const int* __restrict__ dst2, const int* __restrict__ et2, int e2n) {
    int idx = blockIdx.x * blockDim.x + threadIdx.x;
    int stride = gridDim.x * blockDim.x;
    const int4* d14 = (const int4*)dst1;
    int n4 = e1n >> 2;
    for (int i = idx; i < n4; i += stride) {
        int4 dd = __ldg(d14 + i);
        int m0 = __ldg(hmap + dd.x), m1 = __ldg(hmap + dd.y);
        int m2 = __ldg(hmap + dd.z), m3 = __ldg(hmap + dd.w);
        if (m0 < 0) g_q[atomicAdd(&g_qcount, 1)] = 4*i + 0;
        if (m1 < 0) g_q[atomicAdd(&g_qcount, 1)] = 4*i + 1;
        if (m2 < 0) g_q[atomicAdd(&g_qcount, 1)] = 4*i + 2;
        if (m3 < 0) g_q[atomicAdd(&g_qcount, 1)] = 4*i + 3;
    }
    for (int e = (n4 << 2) + idx; e < e1n; e += stride)
        if (__ldg(hmap + __ldg(dst1 + e)) < 0)
            g_q[atomicAdd(&g_qcount, 1)] = e;
    // layer-2 histogram
    const int4* d24 = (const int4*)dst2;
    const int4* t24 = (const int4*)et2;
    int h4 = e2n >> 2;
    for (int i = idx; i < h4; i += stride) {
        int4 dd = __ldg(d24 + i);
        int4 tt = __ldg(t24 + i);
        atomicAdd(&g_counts[dd.x * RR + tt.x], 1);
        atomicAdd(&g_counts[dd.y * RR + tt.y], 1);
        atomicAdd(&g_counts[dd.z * RR + tt.z], 1);
        atomicAdd(&g_counts[dd.w * RR + tt.w], 1);
    }
    for (int e = (h4 << 2) + idx; e < e2n; e += stride)
        atomicAdd(&g_counts[__ldg(dst2 + e) * RR + __ldg(et2 + e)], 1);
}

// ---------------- KNEEDY: self-transform + edge messages for needy rows ---
// Work items: [0, ncount) self rows (x[d] @ Wself1 + b1),
//             [ncount, ncount+qcount) edges (x[src] @ W1[r]).
// All contributions atomicAdd into zero-initialized g_h rows (commutative).
// 512 threads: col t = tid&127, K-quarter q = tid>>7 (32 loads per thread),
// then 4-way smem reduction.
__global__ void __launch_bounds__(512) kneedy(const float* __restrict__ x,
                                              const int* __restrict__ src1,
                                              const int* __restrict__ dst1,
                                              const int* __restrict__ et1,
                                              const float* __restrict__ W1,
                                              const float* __restrict__ Wself1,
                                              const float* __restrict__ b1) {
    __shared__ float xs[DIN];
    __shared__ float part[3][DIN];
    int tid = threadIdx.x;
    int t = tid & 127;
    int q = tid >> 7;                            // 0..3
    int ncount = g_ncount;
    int total = ncount + g_qcount;
    for (int item = blockIdx.x; item < total; item += gridDim.x) {
        int d, s;
        const float* W;
        bool self = (item < ncount);
        if (self) {
            d = g_needy[item];
            s = d;
            W = Wself1;
        } else {
            int e = g_q[item - ncount];
            s = src1[e]; d = dst1[e];
            W = W1 + (size_t)et1[e] * DIN * DH;
        }
        if (tid < DIN) xs[tid] = x[(size_t)s * DIN + tid];
        __syncthreads();
        int base = q * 32;
        const float* w = W + (size_t)base * DH + t;
        float a0 = 0.f, a1 = 0.f, a2 = 0.f, a3 = 0.f;
        #pragma unroll
        for (int i = 0; i < 32; i += 4) {
            a0 = fmaf(xs[base + i + 0], w[(i + 0) * DH], a0);
            a1 = fmaf(xs[base + i + 1], w[(i + 1) * DH], a1);
            a2 = fmaf(xs[base + i + 2], w[(i + 2) * DH], a2);
            a3 = fmaf(xs[base + i + 3], w[(i + 3) * DH], a3);
        }
        float acc = (a0 + a1) + (a2 + a3);
        if (q) part[q - 1][t] = acc;
        __syncthreads();
        if (!q) {
            float v = acc + part[0][t] + part[1][t] + part[2][t];
            if (self) v += b1[t];
            atomicAdd(&g_h[(size_t)d * DH + t], v);
        }
        __syncthreads();
    }
}

// ---------------- C3: needy BN patch + BN params + exclusive scan ---------
__global__ void c3_scan_bn(const float* __restrict__ gamma,
                           const float* __restrict__ beta) {
    int t = threadIdx.x;                          // 1024 threads
    if (t < DH) {
        float s = 0.f, ss = 0.f;
        int n = g_ncount;
        for (int j = 0; j < n; j++) {
            float v = g_h[(size_t)g_needy[j] * DH + t];
            s += v;
            ss = fmaf(v, v, ss);
        }
        float sum = g_bnsum[t] + s;
        float sq  = g_bnsq[t] + ss;
        float mean = sum * (1.0f / N1);
        float var  = sq * (1.0f / N1) - mean * mean;
        float sc   = gamma[t] * rsqrtf(var + BN_EPS);
        g_scale[t] = sc;
        g_shift[t] = beta[t] - mean * sc;
    }
    __shared__ int part[1024];
    const int CH = (NKEYS + 1023) / 1024;        // 24
    int beg = t * CH;
    int end = min(beg + CH, NKEYS);
    int s = 0;
    for (int i = beg; i < end; i++) s += g_counts[i];
    part[t] = s;
    __syncthreads();
    for (int off = 1; off < 1024; off <<= 1) {
        int v = (t >= off) ? part[t - off] : 0;
        __syncthreads();
        part[t] += v;
        __syncthreads();
    }
    int run = part[t] - s;                        // exclusive prefix
    for (int i = beg; i < end; i++) {
        g_offsets[i] = run;
        g_cursor[i]  = run;
        run += g_counts[i];
    }
    if (t == 1023) g_offsets[NKEYS] = part[1023];
}

// ---------------- C4: scatter edge srcs into segment order ----------------
__global__ void __launch_bounds__(256) c4_scatter(
        const int* __restrict__ src2, const int* __restrict__ dst2,
        const int* __restrict__ et2, int e2n) {
    int idx = blockIdx.x * blockDim.x + threadIdx.x;
    int stride = gridDim.x * blockDim.x;
    const int4* s4 = (const int4*)src2;
    const int4* d4 = (const int4*)dst2;
    const int4* t4 = (const int4*)et2;
    int n4 = e2n >> 2;
    for (int i = idx; i < n4; i += stride) {
        int4 ss = __ldg(s4 + i);
        int4 dd = __ldg(d4 + i);
        int4 tt = __ldg(t4 + i);
        g_esrc[atomicAdd(&g_cursor[dd.x * RR + tt.x], 1)] = ss.x;
        g_esrc[atomicAdd(&g_cursor[dd.y * RR + tt.y], 1)] = ss.y;
        g_esrc[atomicAdd(&g_cursor[dd.z * RR + tt.z], 1)] = ss.z;
        g_esrc[atomicAdd(&g_cursor[dd.w * RR + tt.w], 1)] = ss.w;
    }
    for (int e = (n4 << 2) + idx; e < e2n; e += stride) {
        int key = __ldg(dst2 + e) * RR + __ldg(et2 + e);
        g_esrc[atomicAdd(&g_cursor[key], 1)] = __ldg(src2 + e);
    }
}

// ---------------- K5a: per-(dst,rel) aggregation, one warp per segment ----
// Lane l owns cols [4l, 4l+4) as float4; 8 segments per 256-thread block.
__global__ void __launch_bounds__(256) k5a_agg() {
    int w = threadIdx.x >> 5;
    int l = threadIdx.x & 31;
    int seg = blockIdx.x * 8 + w;
    if (seg >= NKEYS) return;
    int d = seg >> 2, r = seg & 3;
    float4 sc = *(const float4*)&g_scale[4 * l];
    float4 sh = *(const float4*)&g_shift[4 * l];
    int beg = g_offsets[seg], end = g_offsets[seg + 1];
    float4 acc = make_float4(0.f, 0.f, 0.f, 0.f);
    int j = beg;
    for (; j + 4 <= end; j += 4) {
        int s0 = g_esrc[j + 0], s1 = g_esrc[j + 1];
        int s2 = g_esrc[j + 2], s3 = g_esrc[j + 3];
        float4 v0 = *(const float4*)&g_h[(size_t)s0 * DH + 4 * l];
        float4 v1 = *(const float4*)&g_h[(size_t)s1 * DH + 4 * l];
        float4 v2 = *(const float4*)&g_h[(size_t)s2 * DH + 4 * l];
        float4 v3 = *(const float4*)&g_h[(size_t)s3 * DH + 4 * l];
        acc.x += fmaxf(fmaf(sc.x, v0.x, sh.x), 0.f) + fmaxf(fmaf(sc.x, v1.x, sh.x), 0.f)
               + fmaxf(fmaf(sc.x, v2.x, sh.x), 0.f) + fmaxf(fmaf(sc.x, v3.x, sh.x), 0.f);
        acc.y += fmaxf(fmaf(sc.y, v0.y, sh.y), 0.f) + fmaxf(fmaf(sc.y, v1.y, sh.y), 0.f)
               + fmaxf(fmaf(sc.y, v2.y, sh.y), 0.f) + fmaxf(fmaf(sc.y, v3.y, sh.y), 0.f);
        acc.z += fmaxf(fmaf(sc.z, v0.z, sh.z), 0.f) + fmaxf(fmaf(sc.z, v1.z, sh.z), 0.f)
               + fmaxf(fmaf(sc.z, v2.z, sh.z), 0.f) + fmaxf(fmaf(sc.z, v3.z, sh.z), 0.f);
        acc.w += fmaxf(fmaf(sc.w, v0.w, sh.w), 0.f) + fmaxf(fmaf(sc.w, v1.w, sh.w), 0.f)
               + fmaxf(fmaf(sc.w, v2.w, sh.w), 0.f) + fmaxf(fmaf(sc.w, v3.w, sh.w), 0.f);
    }
    for (; j < end; j++) {
        float4 v = *(const float4*)&g_h[(size_t)g_esrc[j] * DH + 4 * l];
        acc.x += fmaxf(fmaf(sc.x, v.x, sh.x), 0.f);
        acc.y += fmaxf(fmaf(sc.y, v.y, sh.y), 0.f);
        acc.z += fmaxf(fmaf(sc.z, v.z, sh.z), 0.f);
        acc.w += fmaxf(fmaf(sc.w, v.w, sh.w), 0.f);
    }
    float* Ad = g_A + (size_t)d * KTOT;
    *(float4*)&Ad[r * DH + 4 * l] = acc;
    if (r == 0) {                                // self-loop (d < N2 <= N1)
        float4 v = *(const float4*)&g_h[(size_t)d * DH + 4 * l];
        float4 sv = make_float4(fmaxf(fmaf(sc.x, v.x, sh.x), 0.f),
                                fmaxf(fmaf(sc.y, v.y, sh.y), 0.f),
                                fmaxf(fmaf(sc.z, v.z, sh.z), 0.f),
                                fmaxf(fmaf(sc.w, v.w, sh.w), 0.f));
        *(float4*)&Ad[RR * DH + 4 * l] = sv;
    }
}

// ---------------- K5b: tiled GEMM [6000,640]x[640,64] + bias + log-softmax
#define TMB 32
#define KB  16
#define NCH (KTOT / KB)      // 40

__global__ void __launch_bounds__(128) k5b_gemm(const float* __restrict__ W2,
                                                const float* __restrict__ Wself2,
                                                const float* __restrict__ b2,
                                                float* __restrict__ out) {
    __shared__ float As[KB][TMB + 4];            // stride 36 floats
    __shared__ float Ws[KB][DOUT];
    int tid = threadIdx.x;
    int tc = tid & 15;                           // col group (4 cols)
    int tr = tid >> 4;                           // row group (4 rows), 0..7
    int row0 = blockIdx.x * TMB;

    int m_l = tid >> 2;                          // 0..31
    int k_l = (tid & 3) * 4;                     // 0,4,8,12
    int arow = min(row0 + m_l, N2 - 1);
    const float* Ab = g_A + (size_t)arow * KTOT + k_l;

    int k_w = tid >> 3;                          // 0..15
    int c_w = (tid & 7) * 8;                     // 0..56

    float4 pa, pw0, pw1;
    pa = *(const float4*)Ab;
    {
        const float* wp = W2 + (size_t)k_w * DOUT + c_w;   // chunk 0: k < 512
        pw0 = *(const float4*)wp;
        pw1 = *(const float4*)(wp + 4);
    }

    float acc[4][4];
    #pragma unroll
    for (int m = 0; m < 4; m++)
        #pragma unroll
        for (int c = 0; c < 4; c++) acc[m][c] = 0.f;

    for (int kc = 0; kc < NCH; kc++) {
        __syncthreads();
        As[k_l + 0][m_l] = pa.x;
        As[k_l + 1][m_l] = pa.y;
        As[k_l + 2][m_l] = pa.z;
        As[k_l + 3][m_l] = pa.w;
        *(float4*)&Ws[k_w][c_w]     = pw0;
        *(float4*)&Ws[k_w][c_w + 4] = pw1;
        __syncthreads();
        if (kc + 1 < NCH) {
            pa = *(const float4*)(Ab + (kc + 1) * KB);
            int kk = (kc + 1) * KB + k_w;
            const float* wp = (kk < RR * DH)
                ? W2 + (size_t)kk * DOUT + c_w
                : Wself2 + (size_t)(kk - RR * DH) * DOUT + c_w;
            pw0 = *(const float4*)wp;
            pw1 = *(const float4*)(wp + 4);
        }
        #pragma unroll
        for (int k = 0; k < KB; k++) {
            float4 a = *(float4*)&As[k][tr * 4];
            float4 w = *(float4*)&Ws[k][tc * 4];
            acc[0][0] = fmaf(a.x, w.x, acc[0][0]);
            acc[0][1] = fmaf(a.x, w.y, acc[0][1]);
            acc[0][2] = fmaf(a.x, w.z, acc[0][2]);
            acc[0][3] = fmaf(a.x, w.w, acc[0][3]);
            acc[1][0] = fmaf(a.y, w.x, acc[1][0]);
            acc[1][1] = fmaf(a.y, w.y, acc[1][1]);
            acc[1][2] = fmaf(a.y, w.z, acc[1][2]);
            acc[1][3] = fmaf(a.y, w.w, acc[1][3]);
            acc[2][0] = fmaf(a.z, w.x, acc[2][0]);
            acc[2][1] = fmaf(a.z, w.y, acc[2][1]);
            acc[2][2] = fmaf(a.z, w.z, acc[2][2]);
            acc[2][3] = fmaf(a.z, w.w, acc[2][3]);
            acc[3][0] = fmaf(a.w, w.x, acc[3][0]);
            acc[3][1] = fmaf(a.w, w.y, acc[3][1]);
            acc[3][2] = fmaf(a.w, w.z, acc[3][2]);
            acc[3][3] = fmaf(a.w, w.w, acc[3][3]);
        }
    }

    // epilogue: bias + log-softmax per row (16 lanes share one row)
    float4 bb = *(const float4*)(b2 + tc * 4);
    #pragma unroll
    for (int m = 0; m < 4; m++) {
        int row = row0 + tr * 4 + m;
        float v0 = acc[m][0] + bb.x;
        float v1 = acc[m][1] + bb.y;
        float v2 = acc[m][2] + bb.z;
        float v3 = acc[m][3] + bb.w;
        float mx = fmaxf(fmaxf(v0, v1), fmaxf(v2, v3));
        #pragma unroll
        for (int off = 1; off < 16; off <<= 1)
            mx = fmaxf(mx, __shfl_xor_sync(0xffffffffu, mx, off));
        float es = expf(v0 - mx) + expf(v1 - mx) + expf(v2 - mx) + expf(v3 - mx);
        #pragma unroll
        for (int off = 1; off < 16; off <<= 1)
            es += __shfl_xor_sync(0xffffffffu, es, off);
        float l = mx + logf(es);
        if (row < N2) {
            float4 o = make_float4(v0 - l, v1 - l, v2 - l, v3 - l);
            *(float4*)(out + (size_t)row * DOUT + tc * 4) = o;
        }
    }
}

// ---------------- launch ---------------------------------------------------
extern "C" void kernel_launch(void* const* d_in, const int* in_sizes, int n_in,
                              void* d_out, int out_size) {
    const float* x      = (const float*)d_in[0];
    const int*   src1   = (const int*)d_in[1];
    const int*   dst1   = (const int*)d_in[2];
    const int*   et1    = (const int*)d_in[3];
    const int*   src2   = (const int*)d_in[4];
    const int*   dst2   = (const int*)d_in[5];
    const int*   et2    = (const int*)d_in[6];
    const int*   hmap   = (const int*)d_in[7];
    const float* hist   = (const float*)d_in[8];
    const float* W1     = (const float*)d_in[9];
    const float* Wself1 = (const float*)d_in[10];
    const float* b1     = (const float*)d_in[11];
    const float* gamma  = (const float*)d_in[12];
    const float* beta   = (const float*)d_in[13];
    const float* W2     = (const float*)d_in[14];
    const float* Wself2 = (const float*)d_in[15];
    const float* b2     = (const float*)d_in[16];
    float* out = (float*)d_out;

    int e1n = in_sizes[1];
    int e2n = in_sizes[4];

    k0_zero<<<96, 256>>>();
    k1_gather<<<512, 256>>>(hmap, (const float4*)hist);
    k2a_scan<<<2048, 256>>>(dst1, hmap, e1n, dst2, et2, e2n);
    kneedy<<<64, 512>>>(x, src1, dst1, et1, W1, Wself1, b1);
    c3_scan_bn<<<1, 1024>>>(gamma, beta);
    c4_scatter<<<1024, 256>>>(src2, dst2, et2, e2n);
    k5a_agg<<<(NKEYS + 7) / 8, 256>>>();
    k5b_gemm<<<(N2 + TMB - 1) / TMB, 128>>>(W2, Wself2, b2, out);
}

// round 9
// speedup vs baseline: 1.5574x; 1.1247x over previous
#include <cuda_runtime.h>
#include <math.h>

// Problem constants (fixed by the dataset)
#define N0   300000
#define N1   60000
#define N2   6000
#define E1C  1200000
#define E2C  300000
#define RR   4
#define DIN  128
#define DH   128
#define DOUT 64
#define NKEYS (N2*RR)          // 24000 (d,r) segments
#define KTOT  (RR*DH + DH)     // 640 concat K for layer-2 GEMM
#define BN_EPS 1e-5f

// ---------------- scratch (static device globals; no runtime allocation) ----
static __device__ __align__(16) float g_h[(size_t)N1 * DH];   // layer-1 output
static __device__ __align__(16) float g_A[(size_t)N2 * KTOT]; // layer-2 aggregates
static __device__ int   g_q[E1C];          // layer-1 edges whose dst is "needy"
static __device__ int   g_qcount;
static __device__ int   g_needy[N1];       // rows with history_map < 0
static __device__ int   g_ncount;
static __device__ float g_bnsum[DH];
static __device__ float g_bnsq[DH];
static __device__ float g_scale[DH];
static __device__ float g_shift[DH];
static __device__ int   g_counts[NKEYS + 1];
static __device__ int   g_offsets[NKEYS + 1];
static __device__ int   g_cursor[NKEYS];
static __device__ int   g_esrc[E2C];       // edge srcs sorted by (dst,rel)

// ---------------- K0: zero per-replay state -------------------------------
__global__ void k0_zero() {
    int i = blockIdx.x * blockDim.x + threadIdx.x;
    int stride = gridDim.x * blockDim.x;
    for (int idx = i; idx <= NKEYS; idx += stride) g_counts[idx] = 0;
    if (i < DH) { g_bnsum[i] = 0.f; g_bnsq[i] = 0.f; }
    if (i == 0) { g_qcount = 0; g_ncount = 0; }
}

// ---------------- K1: h = history gather + BN partial stats + needy list --
// Needy rows (map < 0) are zero-filled so kneedy can accumulate with adds.
__global__ void __launch_bounds__(256) k1_gather(const int* __restrict__ hmap,
                                                 const float4* __restrict__ hist4) {
    float s0=0.f,s1=0.f,s2=0.f,s3=0.f, q0=0.f,q1=0.f,q2=0.f,q3=0.f;
    const int total = N1 * 32;                 // float4 elements
    int stride = gridDim.x * blockDim.x;       // multiple of 32
    for (int i = blockIdx.x * blockDim.x + threadIdx.x; i < total; i += stride) {
        int d = i >> 5;
        int qq = i & 31;
        int m = __ldg(hmap + d);
        if (m >= 0) {
            float4 v = hist4[m * 32 + qq];
            reinterpret_cast<float4*>(g_h)[i] = v;
            s0 += v.x; q0 = fmaf(v.x, v.x, q0);
            s1 += v.y; q1 = fmaf(v.y, v.y, q1);
            s2 += v.z; q2 = fmaf(v.z, v.z, q2);
            s3 += v.w; q3 = fmaf(v.w, v.w, q3);
        } else {
            reinterpret_cast<float4*>(g_h)[i] = make_float4(0.f, 0.f, 0.f, 0.f);
            if (qq == 0) {
                int p = atomicAdd(&g_ncount, 1);
                g_needy[p] = d;
            }
        }
    }
    __shared__ float red[256][4];
    int t = threadIdx.x;
    red[t][0]=s0; red[t][1]=s1; red[t][2]=s2; red[t][3]=s3;
    __syncthreads();
    if (t < 32) {
        float a0=0.f,a1=0.f,a2=0.f,a3=0.f;
        #pragma unroll
        for (int w = 0; w < 8; w++) {
            a0 += red[t+32*w][0]; a1 += red[t+32*w][1];
            a2 += red[t+32*w][2]; a3 += red[t+32*w][3];
        }
        atomicAdd(&g_bnsum[t*4+0], a0); atomicAdd(&g_bnsum[t*4+1], a1);
        atomicAdd(&g_bnsum[t*4+2], a2); atomicAdd(&g_bnsum[t*4+3], a3);
    }
    __syncthreads();
    red[t][0]=q0; red[t][1]=q1; red[t][2]=q2; red[t][3]=q3;
    __syncthreads();
    if (t < 32) {
        float a0=0.f,a1=0.f,a2=0.f,a3=0.f;
        #pragma unroll
        for (int w = 0; w < 8; w++) {
            a0 += red[t+32*w][0]; a1 += red[t+32*w][1];
            a2 += red[t+32*w][2]; a3 += red[t+32*w][3];
        }
        atomicAdd(&g_bnsq[t*4+0], a0); atomicAdd(&g_bnsq[t*4+1], a1);
        atomicAdd(&g_bnsq[t*4+2], a2); atomicAdd(&g_bnsq[t*4+3], a3);
    }
}

// ---------------- K2a: scan layer-1 edges for needy dsts + layer-2 hist ---
__global__ void __launch_bounds__(256) k2a_scan(
        const int* __restrict__ dst1, const int* __restrict__ hmap, int e1n,
        const int* __restrict__ dst2, const int* __restrict__ et2, int e2n) {
    int idx = blockIdx.x * blockDim.x + threadIdx.x;
    int stride = gridDim.x * blockDim.x;
    const int4* d14 = (const int4*)dst1;
    int n4 = e1n >> 2;
    for (int i = idx; i < n4; i += stride) {
        int4 dd = __ldg(d14 + i);
        int m0 = __ldg(hmap + dd.x), m1 = __ldg(hmap + dd.y);
        int m2 = __ldg(hmap + dd.z), m3 = __ldg(hmap + dd.w);
        if (m0 < 0) g_q[atomicAdd(&g_qcount, 1)] = 4*i + 0;
        if (m1 < 0) g_q[atomicAdd(&g_qcount, 1)] = 4*i + 1;
        if (m2 < 0) g_q[atomicAdd(&g_qcount, 1)] = 4*i + 2;
        if (m3 < 0) g_q[atomicAdd(&g_qcount, 1)] = 4*i + 3;
    }
    for (int e = (n4 << 2) + idx; e < e1n; e += stride)
        if (__ldg(hmap + __ldg(dst1 + e)) < 0)
            g_q[atomicAdd(&g_qcount, 1)] = e;
    // layer-2 histogram
    const int4* d24 = (const int4*)dst2;
    const int4* t24 = (const int4*)et2;
    int h4 = e2n >> 2;
    for (int i = idx; i < h4; i += stride) {
        int4 dd = __ldg(d24 + i);
        int4 tt = __ldg(t24 + i);
        atomicAdd(&g_counts[dd.x * RR + tt.x], 1);
        atomicAdd(&g_counts[dd.y * RR + tt.y], 1);
        atomicAdd(&g_counts[dd.z * RR + tt.z], 1);
        atomicAdd(&g_counts[dd.w * RR + tt.w], 1);
    }
    for (int e = (h4 << 2) + idx; e < e2n; e += stride)
        atomicAdd(&g_counts[__ldg(dst2 + e) * RR + __ldg(et2 + e)], 1);
}

// ---------------- KNEEDY: self-transform + edge messages for needy rows ---
__global__ void __launch_bounds__(512) kneedy(const float* __restrict__ x,
                                              const int* __restrict__ src1,
                                              const int* __restrict__ dst1,
                                              const int* __restrict__ et1,
                                              const float* __restrict__ W1,
                                              const float* __restrict__ Wself1,
                                              const float* __restrict__ b1) {
    __shared__ float xs[DIN];
    __shared__ float part[3][DIN];
    int tid = threadIdx.x;
    int t = tid & 127;
    int q = tid >> 7;                            // 0..3
    int ncount = g_ncount;
    int total = ncount + g_qcount;
    for (int item = blockIdx.x; item < total; item += gridDim.x) {
        int d, s;
        const float* W;
        bool self = (item < ncount);
        if (self) {
            d = g_needy[item];
            s = d;
            W = Wself1;
        } else {
            int e = g_q[item - ncount];
            s = src1[e]; d = dst1[e];
            W = W1 + (size_t)et1[e] * DIN * DH;
        }
        if (tid < DIN) xs[tid] = x[(size_t)s * DIN + tid];
        __syncthreads();
        int base = q * 32;
        const float* w = W + (size_t)base * DH + t;
        float a0 = 0.f, a1 = 0.f, a2 = 0.f, a3 = 0.f;
        #pragma unroll
        for (int i = 0; i < 32; i += 4) {
            a0 = fmaf(xs[base + i + 0], w[(i + 0) * DH], a0);
            a1 = fmaf(xs[base + i + 1], w[(i + 1) * DH], a1);
            a2 = fmaf(xs[base + i + 2], w[(i + 2) * DH], a2);
            a3 = fmaf(xs[base + i + 3], w[(i + 3) * DH], a3);
        }
        float acc = (a0 + a1) + (a2 + a3);
        if (q) part[q - 1][t] = acc;
        __syncthreads();
        if (!q) {
            float v = acc + part[0][t] + part[1][t] + part[2][t];
            if (self) v += b1[t];
            atomicAdd(&g_h[(size_t)d * DH + t], v);
        }
        __syncthreads();
    }
}

// ---------------- KBN: needy BN patch + BN params (tiny, after kneedy) ----
__global__ void kbn(const float* __restrict__ gamma,
                    const float* __restrict__ beta) {
    int t = threadIdx.x;                         // 128 threads, 1 block
    float s = 0.f, ss = 0.f;
    int n = g_ncount;
    for (int j = 0; j < n; j++) {
        float v = g_h[(size_t)g_needy[j] * DH + t];
        s += v;
        ss = fmaf(v, v, ss);
    }
    float sum = g_bnsum[t] + s;
    float sq  = g_bnsq[t] + ss;
    float mean = sum * (1.0f / N1);
    float var  = sq * (1.0f / N1) - mean * mean;
    float sc   = gamma[t] * rsqrtf(var + BN_EPS);
    g_scale[t] = sc;
    g_shift[t] = beta[t] - mean * sc;
}

// ---------------- C3: single-block exclusive scan over counts -------------
__global__ void c3_scan() {
    int t = threadIdx.x;                          // 1024 threads
    __shared__ int part[1024];
    const int CH = (NKEYS + 1023) / 1024;        // 24
    int beg = t * CH;
    int end = min(beg + CH, NKEYS);
    int s = 0;
    for (int i = beg; i < end; i++) s += g_counts[i];
    part[t] = s;
    __syncthreads();
    for (int off = 1; off < 1024; off <<= 1) {
        int v = (t >= off) ? part[t - off] : 0;
        __syncthreads();
        part[t] += v;
        __syncthreads();
    }
    int run = part[t] - s;                        // exclusive prefix
    for (int i = beg; i < end; i++) {
        g_offsets[i] = run;
        g_cursor[i]  = run;
        run += g_counts[i];
    }
    if (t == 1023) g_offsets[NKEYS] = part[1023];
}

// ---------------- C4: scatter edge srcs into segment order ----------------
__global__ void __launch_bounds__(256) c4_scatter(
        const int* __restrict__ src2, const int* __restrict__ dst2,
        const int* __restrict__ et2, int e2n) {
    int idx = blockIdx.x * blockDim.x + threadIdx.x;
    int stride = gridDim.x * blockDim.x;
    const int4* s4 = (const int4*)src2;
    const int4* d4 = (const int4*)dst2;
    const int4* t4 = (const int4*)et2;
    int n4 = e2n >> 2;
    for (int i = idx; i < n4; i += stride) {
        int4 ss = __ldg(s4 + i);
        int4 dd = __ldg(d4 + i);
        int4 tt = __ldg(t4 + i);
        g_esrc[atomicAdd(&g_cursor[dd.x * RR + tt.x], 1)] = ss.x;
        g_esrc[atomicAdd(&g_cursor[dd.y * RR + tt.y], 1)] = ss.y;
        g_esrc[atomicAdd(&g_cursor[dd.z * RR + tt.z], 1)] = ss.z;
        g_esrc[atomicAdd(&g_cursor[dd.w * RR + tt.w], 1)] = ss.w;
    }
    for (int e = (n4 << 2) + idx; e < e2n; e += stride) {
        int key = __ldg(dst2 + e) * RR + __ldg(et2 + e);
        g_esrc[atomicAdd(&g_cursor[key], 1)] = __ldg(src2 + e);
    }
}

// ---------------- K5a: per-(dst,rel) aggregation, one warp per segment ----
__global__ void __launch_bounds__(256) k5a_agg() {
    int w = threadIdx.x >> 5;
    int l = threadIdx.x & 31;
    int seg = blockIdx.x * 8 + w;
    if (seg >= NKEYS) return;
    int d = seg >> 2, r = seg & 3;
    float4 sc = *(const float4*)&g_scale[4 * l];
    float4 sh = *(const float4*)&g_shift[4 * l];
    int beg = g_offsets[seg], end = g_offsets[seg + 1];
    float4 acc = make_float4(0.f, 0.f, 0.f, 0.f);
    int j = beg;
    for (; j + 4 <= end; j += 4) {
        int s0 = g_esrc[j + 0], s1 = g_esrc[j + 1];
        int s2 = g_esrc[j + 2], s3 = g_esrc[j + 3];
        float4 v0 = *(const float4*)&g_h[(size_t)s0 * DH + 4 * l];
        float4 v1 = *(const float4*)&g_h[(size_t)s1 * DH + 4 * l];
        float4 v2 = *(const float4*)&g_h[(size_t)s2 * DH + 4 * l];
        float4 v3 = *(const float4*)&g_h[(size_t)s3 * DH + 4 * l];
        acc.x += fmaxf(fmaf(sc.x, v0.x, sh.x), 0.f) + fmaxf(fmaf(sc.x, v1.x, sh.x), 0.f)
               + fmaxf(fmaf(sc.x, v2.x, sh.x), 0.f) + fmaxf(fmaf(sc.x, v3.x, sh.x), 0.f);
        acc.y += fmaxf(fmaf(sc.y, v0.y, sh.y), 0.f) + fmaxf(fmaf(sc.y, v1.y, sh.y), 0.f)
               + fmaxf(fmaf(sc.y, v2.y, sh.y), 0.f) + fmaxf(fmaf(sc.y, v3.y, sh.y), 0.f);
        acc.z += fmaxf(fmaf(sc.z, v0.z, sh.z), 0.f) + fmaxf(fmaf(sc.z, v1.z, sh.z), 0.f)
               + fmaxf(fmaf(sc.z, v2.z, sh.z), 0.f) + fmaxf(fmaf(sc.z, v3.z, sh.z), 0.f);
        acc.w += fmaxf(fmaf(sc.w, v0.w, sh.w), 0.f) + fmaxf(fmaf(sc.w, v1.w, sh.w), 0.f)
               + fmaxf(fmaf(sc.w, v2.w, sh.w), 0.f) + fmaxf(fmaf(sc.w, v3.w, sh.w), 0.f);
    }
    for (; j < end; j++) {
        float4 v = *(const float4*)&g_h[(size_t)g_esrc[j] * DH + 4 * l];
        acc.x += fmaxf(fmaf(sc.x, v.x, sh.x), 0.f);
        acc.y += fmaxf(fmaf(sc.y, v.y, sh.y), 0.f);
        acc.z += fmaxf(fmaf(sc.z, v.z, sh.z), 0.f);
        acc.w += fmaxf(fmaf(sc.w, v.w, sh.w), 0.f);
    }
    float* Ad = g_A + (size_t)d * KTOT;
    *(float4*)&Ad[r * DH + 4 * l] = acc;
    if (r == 0) {                                // self-loop (d < N2 <= N1)
        float4 v = *(const float4*)&g_h[(size_t)d * DH + 4 * l];
        float4 sv = make_float4(fmaxf(fmaf(sc.x, v.x, sh.x), 0.f),
                                fmaxf(fmaf(sc.y, v.y, sh.y), 0.f),
                                fmaxf(fmaf(sc.z, v.z, sh.z), 0.f),
                                fmaxf(fmaf(sc.w, v.w, sh.w), 0.f));
        *(float4*)&Ad[RR * DH + 4 * l] = sv;
    }
}

// ---------------- K5b: tiled GEMM [6000,640]x[640,64] + bias + log-softmax
#define TMB 32
#define KB  16
#define NCH (KTOT / KB)      // 40

__global__ void __launch_bounds__(128) k5b_gemm(const float* __restrict__ W2,
                                                const float* __restrict__ Wself2,
                                                const float* __restrict__ b2,
                                                float* __restrict__ out) {
    __shared__ float As[KB][TMB + 4];            // stride 36 floats
    __shared__ float Ws[KB][DOUT];
    int tid = threadIdx.x;
    int tc = tid & 15;                           // col group (4 cols)
    int tr = tid >> 4;                           // row group (4 rows), 0..7
    int row0 = blockIdx.x * TMB;

    int m_l = tid >> 2;                          // 0..31
    int k_l = (tid & 3) * 4;                     // 0,4,8,12
    int arow = min(row0 + m_l, N2 - 1);
    const float* Ab = g_A + (size_t)arow * KTOT + k_l;

    int k_w = tid >> 3;                          // 0..15
    int c_w = (tid & 7) * 8;                     // 0..56

    float4 pa, pw0, pw1;
    pa = *(const float4*)Ab;
    {
        const float* wp = W2 + (size_t)k_w * DOUT + c_w;   // chunk 0: k < 512
        pw0 = *(const float4*)wp;
        pw1 = *(const float4*)(wp + 4);
    }

    float acc[4][4];
    #pragma unroll
    for (int m = 0; m < 4; m++)
        #pragma unroll
        for (int c = 0; c < 4; c++) acc[m][c] = 0.f;

    for (int kc = 0; kc < NCH; kc++) {
        __syncthreads();
        As[k_l + 0][m_l] = pa.x;
        As[k_l + 1][m_l] = pa.y;
        As[k_l + 2][m_l] = pa.z;
        As[k_l + 3][m_l] = pa.w;
        *(float4*)&Ws[k_w][c_w]     = pw0;
        *(float4*)&Ws[k_w][c_w + 4] = pw1;
        __syncthreads();
        if (kc + 1 < NCH) {
            pa = *(const float4*)(Ab + (kc + 1) * KB);
            int kk = (kc + 1) * KB + k_w;
            const float* wp = (kk < RR * DH)
                ? W2 + (size_t)kk * DOUT + c_w
                : Wself2 + (size_t)(kk - RR * DH) * DOUT + c_w;
            pw0 = *(const float4*)wp;
            pw1 = *(const float4*)(wp + 4);
        }
        #pragma unroll
        for (int k = 0; k < KB; k++) {
            float4 a = *(float4*)&As[k][tr * 4];
            float4 w = *(float4*)&Ws[k][tc * 4];
            acc[0][0] = fmaf(a.x, w.x, acc[0][0]);
            acc[0][1] = fmaf(a.x, w.y, acc[0][1]);
            acc[0][2] = fmaf(a.x, w.z, acc[0][2]);
            acc[0][3] = fmaf(a.x, w.w, acc[0][3]);
            acc[1][0] = fmaf(a.y, w.x, acc[1][0]);
            acc[1][1] = fmaf(a.y, w.y, acc[1][1]);
            acc[1][2] = fmaf(a.y, w.z, acc[1][2]);
            acc[1][3] = fmaf(a.y, w.w, acc[1][3]);
            acc[2][0] = fmaf(a.z, w.x, acc[2][0]);
            acc[2][1] = fmaf(a.z, w.y, acc[2][1]);
            acc[2][2] = fmaf(a.z, w.z, acc[2][2]);
            acc[2][3] = fmaf(a.z, w.w, acc[2][3]);
            acc[3][0] = fmaf(a.w, w.x, acc[3][0]);
            acc[3][1] = fmaf(a.w, w.y, acc[3][1]);
            acc[3][2] = fmaf(a.w, w.z, acc[3][2]);
            acc[3][3] = fmaf(a.w, w.w, acc[3][3]);
        }
    }

    // epilogue: bias + log-softmax per row (16 lanes share one row)
    float4 bb = *(const float4*)(b2 + tc * 4);
    #pragma unroll
    for (int m = 0; m < 4; m++) {
        int row = row0 + tr * 4 + m;
        float v0 = acc[m][0] + bb.x;
        float v1 = acc[m][1] + bb.y;
        float v2 = acc[m][2] + bb.z;
        float v3 = acc[m][3] + bb.w;
        float mx = fmaxf(fmaxf(v0, v1), fmaxf(v2, v3));
        #pragma unroll
        for (int off = 1; off < 16; off <<= 1)
            mx = fmaxf(mx, __shfl_xor_sync(0xffffffffu, mx, off));
        float es = expf(v0 - mx) + expf(v1 - mx) + expf(v2 - mx) + expf(v3 - mx);
        #pragma unroll
        for (int off = 1; off < 16; off <<= 1)
            es += __shfl_xor_sync(0xffffffffu, es, off);
        float l = mx + logf(es);
        if (row < N2) {
            float4 o = make_float4(v0 - l, v1 - l, v2 - l, v3 - l);
            *(float4*)(out + (size_t)row * DOUT + tc * 4) = o;
        }
    }
}

// ---------------- launch: fork/join DAG across two streams ----------------
//   main: k0 ─ k1 ─────(wait evA)─ kneedy ─ kbn ─(wait evB)─ c4 ─ k5a ─ k5b
//   side:   └─ k2a ─[evA]─ c3_scan ─[evB]
// Streams/events are host-side resources created once; the recorded work is
// identical on every call (deterministic), and both streams are joined onto
// the main stream before return.
extern "C" void kernel_launch(void* const* d_in, const int* in_sizes, int n_in,
                              void* d_out, int out_size) {
    const float* x      = (const float*)d_in[0];
    const int*   src1   = (const int*)d_in[1];
    const int*   dst1   = (const int*)d_in[2];
    const int*   et1    = (const int*)d_in[3];
    const int*   src2   = (const int*)d_in[4];
    const int*   dst2   = (const int*)d_in[5];
    const int*   et2    = (const int*)d_in[6];
    const int*   hmap   = (const int*)d_in[7];
    const float* hist   = (const float*)d_in[8];
    const float* W1     = (const float*)d_in[9];
    const float* Wself1 = (const float*)d_in[10];
    const float* b1     = (const float*)d_in[11];
    const float* gamma  = (const float*)d_in[12];
    const float* beta   = (const float*)d_in[13];
    const float* W2     = (const float*)d_in[14];
    const float* Wself2 = (const float*)d_in[15];
    const float* b2     = (const float*)d_in[16];
    float* out = (float*)d_out;

    int e1n = in_sizes[1];
    int e2n = in_sizes[4];

    static cudaStream_t side = 0;
    static cudaEvent_t ev0 = 0, evA = 0, evB = 0;
    if (side == 0) {
        cudaStreamCreateWithFlags(&side, cudaStreamNonBlocking);
        cudaEventCreateWithFlags(&ev0, cudaEventDisableTiming);
        cudaEventCreateWithFlags(&evA, cudaEventDisableTiming);
        cudaEventCreateWithFlags(&evB, cudaEventDisableTiming);
    }
    cudaStream_t main0 = 0;                      // capture-origin (default) stream

    k0_zero<<<96, 256, 0, main0>>>();
    cudaEventRecord(ev0, main0);
    cudaStreamWaitEvent(side, ev0, 0);

    // side branch: edge scan + histogram, then CSR prefix scan
    k2a_scan<<<2048, 256, 0, side>>>(dst1, hmap, e1n, dst2, et2, e2n);
    cudaEventRecord(evA, side);                  // k2a done (g_q, counts ready)
    c3_scan<<<1, 1024, 0, side>>>();
    cudaEventRecord(evB, side);                  // offsets/cursor ready

    // main branch: history gather runs concurrently with k2a
    k1_gather<<<512, 256, 0, main0>>>(hmap, (const float4*)hist);
    cudaStreamWaitEvent(main0, evA, 0);          // kneedy needs g_q + k1 zero-fill
    kneedy<<<64, 512, 0, main0>>>(x, src1, dst1, et1, W1, Wself1, b1);
    kbn<<<1, 128, 0, main0>>>(gamma, beta);      // BN params (needs kneedy + k1)
    cudaStreamWaitEvent(main0, evB, 0);          // c4 needs cursor from scan
    c4_scatter<<<1024, 256, 0, main0>>>(src2, dst2, et2, e2n);
    k5a_agg<<<(NKEYS + 7) / 8, 256, 0, main0>>>();
    k5b_gemm<<<(N2 + TMB - 1) / TMB, 128, 0, main0>>>(W2, Wself2, b2, out);
}